// round 16
// baseline (speedup 1.0000x reference)
#include <cuda_runtime.h>
#include <cuda_fp16.h>
#include <cstdint>

#define BB 4
#define CC 64
#define C8 8
#define NN 9216          // 96*96
#define TN 128           // queries per CTA
#define TM 64            // key/value chunk
#define NCHUNK (NN/TM)   // 144
#define VSTH 80          // Vs row stride (halfs) = 160B

// SMEM layout
#define SOFF_K   0                 // 4 x 1024B K buffers
#define SOFF_V   4096              // 4 x 10240B V buffers
#define SOFF_ATT 45056             // 16384B att quad buffer
#define SMEM_BYTES 61440

// named barrier ids
#define BAR_F 1     // att full   (prod arrive 128 + cons sync 128)
#define BAR_E 2     // att empty  (cons arrive 128 + prod sync 128)
#define BAR_P 3     // producer group (128)
#define BAR_C 4     // consumer group (128)

typedef unsigned long long u64;

// ---------------- scratch ----------------
__device__ __half   g_Qh[(size_t)BB * NN * C8];          // [b][n][k] f16, pre-halved
__device__ __half   g_Kh[(size_t)BB * NCHUNK * TM * C8]; // [b][ch][m][k] f16
__device__ __half   g_Vp[(size_t)BB * NCHUNK * CC * TM]; // [b][ch][c][m'] f16, m-perm
__device__ float    g_vsum[BB * CC];                     // 0.5 * sum_m V_f16
__device__ float    g_sum[BB * CC];                      // sum over n of out (atomic)
__device__ uint32_t g_mxk[BB * CC];                      // max over n (key-coded)

__device__ __forceinline__ float th(float x) {      // MUFU.TANH f32
    asm("tanh.approx.f32 %0, %0;" : "+f"(x));
    return x;
}
__device__ __forceinline__ uint32_t pk(float lo, float hi) {  // f16x2 {lo,hi}
    uint32_t r;
    asm("cvt.rn.f16x2.f32 %0, %1, %2;" : "=r"(r) : "f"(hi), "f"(lo));
    return r;
}
__device__ __forceinline__ uint32_t smem_u32(const void* p) {
    uint32_t a;
    asm("{ .reg .u64 t; cvta.to.shared.u64 t, %1; cvt.u32.u64 %0, t; }" : "=r"(a) : "l"(p));
    return a;
}
__device__ __forceinline__ uint32_t fkey(float f) {
    uint32_t u = __float_as_uint(f);
    return (u >> 31) ? ~u : (u | 0x80000000u);
}
__device__ __forceinline__ float fdec(uint32_t k) {
    return (k >> 31) ? __uint_as_float(k & 0x7FFFFFFFu) : __uint_as_float(~k);
}
__device__ __forceinline__ u64 f2_fma(u64 a, u64 b, u64 c) {
    u64 d;
    asm("fma.rn.f32x2 %0, %1, %2, %3;" : "=l"(d) : "l"(a), "l"(b), "l"(c));
    return d;
}
__device__ __forceinline__ u64 f2_pack(float lo, float hi) {
    u64 d; asm("mov.b64 %0, {%1, %2};" : "=l"(d) : "f"(lo), "f"(hi)); return d;
}
__device__ __forceinline__ void f2_unpack(u64 v, float &lo, float &hi) {
    asm("mov.b64 {%0, %1}, %2;" : "=f"(lo), "=f"(hi) : "l"(v));
}

// m16n8k8 f16 -> f32
__device__ __forceinline__ void mma8h(float d[4], uint32_t a0, uint32_t a1, uint32_t b0) {
    asm volatile(
        "mma.sync.aligned.m16n8k8.row.col.f32.f16.f16.f32 "
        "{%0,%1,%2,%3}, {%4,%5}, {%6}, {%0,%1,%2,%3};"
        : "+f"(d[0]), "+f"(d[1]), "+f"(d[2]), "+f"(d[3])
        : "r"(a0), "r"(a1), "r"(b0));
}
// m16n8k16 f16 -> f32
__device__ __forceinline__ void mma16(float d[4], const uint32_t a[4], uint32_t b0, uint32_t b1) {
    asm volatile(
        "mma.sync.aligned.m16n8k16.row.col.f32.f16.f16.f32 "
        "{%0,%1,%2,%3}, {%4,%5,%6,%7}, {%8,%9}, {%0,%1,%2,%3};"
        : "+f"(d[0]), "+f"(d[1]), "+f"(d[2]), "+f"(d[3])
        : "r"(a[0]), "r"(a[1]), "r"(a[2]), "r"(a[3]), "r"(b0), "r"(b1));
}

#define CP16(dst, src) \
    asm volatile("cp.async.cg.shared.global [%0], [%1], 16;" :: "r"(dst), "l"(src))
#define CP_COMMIT() asm volatile("cp.async.commit_group;" ::: "memory")
#define CP_WAIT0()  asm volatile("cp.async.wait_group 0;" ::: "memory")
#define CP_WAIT1()  asm volatile("cp.async.wait_group 1;" ::: "memory")

#define BARS(id, cnt) asm volatile("bar.sync %0, %1;"   :: "r"(id), "r"(cnt) : "memory")
#define BARA(id, cnt) asm volatile("bar.arrive %0, %1;" :: "r"(id), "r"(cnt) : "memory")
#define STS128(addr, q0, q1, q2, q3) \
    asm volatile("st.shared.v4.b32 [%0], {%1,%2,%3,%4};" \
        :: "r"(addr), "r"(q0), "r"(q1), "r"(q2), "r"(q3) : "memory")

// ---------------- kernel 1: fused 1x1-conv Q/K/V (f32x2 math, f16 outputs) ----
__global__ __launch_bounds__(256) void qkv_kernel(
    const float* __restrict__ x,
    const float* __restrict__ wq, const float* __restrict__ bq,
    const float* __restrict__ wk, const float* __restrict__ bk,
    const float* __restrict__ wv, const float* __restrict__ bv)
{
    __shared__ float sw[80 * 64];
    __shared__ float sb[80];
    int tid = threadIdx.x;
    for (int i = tid; i < 512;  i += 256) sw[i] = wq[i];
    for (int i = tid; i < 512;  i += 256) sw[512 + i] = wk[i];
    for (int i = tid; i < 4096; i += 256) sw[1024 + i] = wv[i];
    if (tid < 80) sb[tid] = (tid < 8) ? bq[tid] : (tid < 16 ? bk[tid - 8] : bv[tid - 16]);
    __syncthreads();

    int n = blockIdx.x * 256 + tid;
    int b = blockIdx.y;
    const float* xb = x + (size_t)b * CC * NN + n;
    u64 xp[32];
    #pragma unroll
    for (int c = 0; c < 32; c++)
        xp[c] = f2_pack(xb[(size_t)(2 * c) * NN], xb[(size_t)(2 * c + 1) * NN]);

    const int ch = n >> 6;
    const int m  = n & 63;
    const int P = (m & 15) >> 1;
    const int mphys = (m & ~15) | ((((P & 3) * 2 + (P >> 2)) << 1) | (m & 1));

    float qv[8], kv[8];
    #pragma unroll 1
    for (int o = 0; o < C8; o++) {
        const u64* wqr = (const u64*)(sw + o * 64);
        const u64* wkr = (const u64*)(sw + 512 + o * 64);
        u64 aq2 = 0ULL, ak2 = 0ULL;
        #pragma unroll
        for (int c = 0; c < 32; c++) {
            aq2 = f2_fma(wqr[c], xp[c], aq2);
            ak2 = f2_fma(wkr[c], xp[c], ak2);
        }
        float ql, qh, kl, kh;
        f2_unpack(aq2, ql, qh); f2_unpack(ak2, kl, kh);
        qv[o] = 0.5f * (sb[o] + ql + qh);       // fold tanh's /2 into Q
        kv[o] = sb[8 + o] + kl + kh;
    }
    {
        uint32_t qw[4], kw[4];
        #pragma unroll
        for (int i = 0; i < 4; i++) {
            qw[i] = pk(qv[2 * i], qv[2 * i + 1]);
            kw[i] = pk(kv[2 * i], kv[2 * i + 1]);
        }
        *(uint4*)(g_Qh + ((size_t)b * NN + n) * C8) = make_uint4(qw[0], qw[1], qw[2], qw[3]);
        *(uint4*)(g_Kh + ((size_t)(b * NCHUNK + ch) * TM + m) * C8) =
            make_uint4(kw[0], kw[1], kw[2], kw[3]);
    }
    __half* vtile = g_Vp + ((size_t)(b * NCHUNK + ch) * CC) * TM;
    #pragma unroll 1
    for (int o = 0; o < CC; o++) {
        const u64* wvr = (const u64*)(sw + 1024 + o * 64);
        u64 av2 = 0ULL;
        #pragma unroll
        for (int c = 0; c < 32; c++) av2 = f2_fma(wvr[c], xp[c], av2);
        float vl, vh;
        f2_unpack(av2, vl, vh);
        vtile[o * TM + mphys] = __float2half_rn(sb[16 + o] + vl + vh);
    }
}

// ---------------- kernel 1b: vsum + zero atomics ----------------
__global__ __launch_bounds__(256) void vsum_kernel()
{
    __shared__ float ss[256];
    int bc = blockIdx.x;
    if (bc == 0) { g_sum[threadIdx.x] = 0.0f; g_mxk[threadIdx.x] = 0u; }
    int b = bc >> 6, c = bc & 63;
    const __half* vb = g_Vp + (size_t)b * NCHUNK * CC * TM + (size_t)c * TM;
    float s = 0.f;
    for (int i = threadIdx.x; i < NCHUNK * TM; i += 256) {
        int ch = i >> 6, m = i & 63;
        s += __half2float(vb[(size_t)ch * CC * TM + m]);
    }
    ss[threadIdx.x] = s;
    __syncthreads();
    for (int o = 128; o > 0; o >>= 1) {
        if (threadIdx.x < o) ss[threadIdx.x] += ss[threadIdx.x + o];
        __syncthreads();
    }
    if (threadIdx.x == 0) g_vsum[bc] = 0.5f * ss[0];
}

// ---------------- kernel 2: warp-specialized tanh-attention -------------------
// warps 0-3 = producers (GEMM1 + tanh -> att quads in SMEM)
// warps 4-7 = consumers (GEMM2, acc over full m), paired 1:1 by 32-n range.
__global__ __launch_bounds__(256, 2) void attn_mma_kernel(
    const float* __restrict__ x, float* __restrict__ out)
{
    extern __shared__ char sh[];
    const uint32_t sb = smem_u32(sh);

    const int tid = threadIdx.x, wid = tid >> 5, lid = tid & 31;
    const int g = lid >> 2, t = lid & 3;
    const int b = blockIdx.y, n0 = blockIdx.x * TN;
    const int role = wid & 3;

    const __half* kbase = g_Kh + (size_t)b * NCHUNK * TM * C8;
    const __half* vbase = g_Vp + (size_t)b * NCHUNK * CC * TM;

    if (wid < 4) {
        // ================= PRODUCER =================
        uint32_t qa[2][2];
        #pragma unroll
        for (int nf = 0; nf < 2; nf++) {
            const uint32_t* q0 = (const uint32_t*)(g_Qh + ((size_t)b * NN + n0 + role * 32 + nf * 16 + g) * C8);
            qa[nf][0] = q0[t];
            qa[nf][1] = q0[t + 32];
        }

        auto stageK = [&](int ch, int buf) {
            if (tid < 64)
                CP16(sb + SOFF_K + buf * 1024 + tid * 16,
                     (const char*)(kbase + (size_t)ch * TM * C8) + tid * 16);
        };

        stageK(0, 0); CP_COMMIT();
        stageK(1, 1); CP_COMMIT();
        CP_WAIT0();
        BARS(BAR_P, 128);

        #pragma unroll 1
        for (int ch = 0; ch < NCHUNK; ch++) {
            const uint32_t* Ks = (const uint32_t*)(sh + SOFF_K + (ch & 3) * 1024);
            uint32_t kb[8];
            #pragma unroll
            for (int mt = 0; mt < 8; mt++)
                kb[mt] = Ks[(mt * 8 + g) * 4 + t];

            uint32_t qd[2][4][4];
            #pragma unroll
            for (int nf = 0; nf < 2; nf++) {
                #pragma unroll
                for (int ks = 0; ks < 4; ks++) {
                    float e0[4], e1[4];
                    e0[0] = e0[1] = e0[2] = e0[3] = 0.0f;
                    e1[0] = e1[1] = e1[2] = e1[3] = 0.0f;
                    mma8h(e0, qa[nf][0], qa[nf][1], kb[2 * ks]);
                    mma8h(e1, qa[nf][0], qa[nf][1], kb[2 * ks + 1]);
                    qd[nf][ks][0] = pk(th(e0[0]), th(e0[1]));
                    qd[nf][ks][1] = pk(th(e0[2]), th(e0[3]));
                    qd[nf][ks][2] = pk(th(e1[0]), th(e1[1]));
                    qd[nf][ks][3] = pk(th(e1[2]), th(e1[3]));
                }
            }

            if (ch > 0) BARS(BAR_E, 256);      // att buffer free
            #pragma unroll
            for (int nf = 0; nf < 2; nf++)
                #pragma unroll
                for (int ks = 0; ks < 4; ks++) {
                    uint32_t a = sb + SOFF_ATT +
                        (uint32_t)((((role * 2 + nf) * 4 + ks) * 32 + lid) * 16);
                    STS128(a, qd[nf][ks][0], qd[nf][ks][1], qd[nf][ks][2], qd[nf][ks][3]);
                }
            BARA(BAR_F, 256);                  // att ready

            if (ch + 2 < NCHUNK) { stageK(ch + 2, (ch + 2) & 3); CP_COMMIT(); CP_WAIT1(); }
            else                 { CP_WAIT0(); }
            BARS(BAR_P, 128);                  // K(ch+1) visible to all producers
        }
        return;   // producers exit
    }

    // ================= CONSUMER =================
    const int tc = tid - 128;

    auto stageV = [&](int ch, int buf) {
        #pragma unroll
        for (int r = 0; r < 4; r++) {
            int pc = tc + r * 128;
            int c = pc >> 3, seg = pc & 7;
            CP16(sb + SOFF_V + buf * 10240 + (uint32_t)(c * 160 + seg * 16),
                 (const char*)(vbase + (size_t)ch * CC * TM + c * TM) + seg * 16);
        }
    };

    stageV(0, 0); CP_COMMIT();
    stageV(1, 1); CP_COMMIT();
    CP_WAIT0();
    BARS(BAR_C, 128);

    float acc[2][8][4];
    #pragma unroll
    for (int nf = 0; nf < 2; nf++)
        #pragma unroll
        for (int j = 0; j < 8; j++)
            #pragma unroll
            for (int k = 0; k < 4; k++) acc[nf][j][k] = 0.0f;

    const uint4* attq = (const uint4*)(sh + SOFF_ATT);

    #pragma unroll 1
    for (int ch = 0; ch < NCHUNK; ch++) {
        const __half* Vs = (const __half*)(sh + SOFF_V + (ch & 3) * 10240);
        BARS(BAR_F, 256);                      // att(ch) ready
        #pragma unroll
        for (int ks = 0; ks < 4; ks++) {
            uint4 a0 = attq[((role * 2 + 0) * 4 + ks) * 32 + lid];
            uint4 a1 = attq[((role * 2 + 1) * 4 + ks) * 32 + lid];
            if (ks == 3 && ch + 1 < NCHUNK) BARA(BAR_E, 256);   // quads in regs
            #pragma unroll
            for (int j = 0; j < 8; j++) {
                uint2 bv = *(const uint2*)(Vs + (8 * j + g) * VSTH + ks * 16 + 4 * t);
                mma16(acc[0][j], (const uint32_t*)&a0, bv.x, bv.y);
                mma16(acc[1][j], (const uint32_t*)&a1, bv.x, bv.y);
            }
        }
        if (ch + 2 < NCHUNK) { stageV(ch + 2, (ch + 2) & 3); CP_COMMIT(); CP_WAIT1(); }
        else                 { CP_WAIT0(); }
        BARS(BAR_C, 128);                      // V(ch+1) visible to all consumers
    }

    // ---- epilogue: out = vsum + 0.5*acc + x; fused mean/max reduction ----
    #pragma unroll
    for (int nf = 0; nf < 2; nf++) {
        const int n = n0 + role * 32 + nf * 16 + g;
        #pragma unroll
        for (int j = 0; j < 8; j++) {
            int c = 8 * j + 2 * t;
            float vs0 = g_vsum[b * CC + c];
            float vs1 = g_vsum[b * CC + c + 1];
            size_t i00 = ((size_t)b * CC + c) * NN + n;
            size_t i01 = i00 + NN;
            float f0  = fmaf(0.5f, acc[nf][j][0], vs0) + x[i00];
            float f1  = fmaf(0.5f, acc[nf][j][1], vs1) + x[i01];
            float f2v = fmaf(0.5f, acc[nf][j][2], vs0) + x[i00 + 8];
            float f3  = fmaf(0.5f, acc[nf][j][3], vs1) + x[i01 + 8];
            out[i00]     = f0;
            out[i01]     = f1;
            out[i00 + 8] = f2v;
            out[i01 + 8] = f3;

            float sc  = f0 + f2v,       sc1 = f1 + f3;
            float mc  = fmaxf(f0, f2v), mc1 = fmaxf(f1, f3);
            #pragma unroll
            for (int off = 16; off >= 4; off >>= 1) {
                sc  += __shfl_down_sync(0xFFFFFFFFu, sc,  off);
                sc1 += __shfl_down_sync(0xFFFFFFFFu, sc1, off);
                mc   = fmaxf(mc,  __shfl_down_sync(0xFFFFFFFFu, mc,  off));
                mc1  = fmaxf(mc1, __shfl_down_sync(0xFFFFFFFFu, mc1, off));
            }
            if (lid < 4) {
                atomicAdd(&g_sum[b * CC + c],     sc);
                atomicAdd(&g_sum[b * CC + c + 1], sc1);
                atomicMax(&g_mxk[b * CC + c],     fkey(mc));
                atomicMax(&g_mxk[b * CC + c + 1], fkey(mc1));
            }
        }
    }
}

// ---------------- kernel 3: CBAM MLP + apply (barrier-free, per-warp MLP) -----
__global__ __launch_bounds__(1024) void apply_scale_kernel(
    float* __restrict__ out,
    const float* __restrict__ w1, const float* __restrict__ w2)
{
    const int bc = blockIdx.x;
    const int b = bc >> 6, c = bc & 63;
    const int tid = threadIdx.x, lane = tid & 31;

    float av0 = g_sum[b * CC + lane]      * (1.0f / NN);
    float av1 = g_sum[b * CC + lane + 32] * (1.0f / NN);
    float mx0 = fdec(g_mxk[b * CC + lane]);
    float mx1 = fdec(g_mxk[b * CC + lane + 32]);

    float y = 0.f;
    #pragma unroll
    for (int r = 0; r < 4; r++) {
        float w0  = w1[r * 64 + lane];
        float w2v = w1[r * 64 + lane + 32];
        float ha = w0 * av0 + w2v * av1;
        float hm = w0 * mx0 + w2v * mx1;
        #pragma unroll
        for (int off = 16; off > 0; off >>= 1) {
            ha += __shfl_xor_sync(0xFFFFFFFFu, ha, off);
            hm += __shfl_xor_sync(0xFFFFFFFFu, hm, off);
        }
        y += w2[c * 4 + r] * (fmaxf(ha, 0.f) + fmaxf(hm, 0.f));
    }
    const float s = 1.0f / (1.0f + expf(-y));

    float4* row = (float4*)(out + (size_t)bc * NN);
    for (int i = tid; i < NN / 4; i += 1024) {
        float4 v = row[i];
        v.x *= s; v.y *= s; v.z *= s; v.w *= s;
        row[i] = v;
    }
}

// ---------------- launch ----------------
extern "C" void kernel_launch(void* const* d_in, const int* in_sizes, int n_in,
                              void* d_out, int out_size)
{
    const float* x     = (const float*)d_in[0];
    const float* wq    = (const float*)d_in[1];
    const float* bq    = (const float*)d_in[2];
    const float* wk    = (const float*)d_in[3];
    const float* bk    = (const float*)d_in[4];
    const float* wv    = (const float*)d_in[5];
    const float* bv    = (const float*)d_in[6];
    const float* ca_w1 = (const float*)d_in[7];
    const float* ca_w2 = (const float*)d_in[8];
    float* out = (float*)d_out;

    cudaFuncSetAttribute(attn_mma_kernel, cudaFuncAttributeMaxDynamicSharedMemorySize, SMEM_BYTES);

    qkv_kernel<<<dim3(NN / 256, BB), 256>>>(x, wq, bq, wk, bk, wv, bv);
    vsum_kernel<<<BB * CC, 256>>>();
    attn_mma_kernel<<<dim3(NN / TN, BB), 256, SMEM_BYTES>>>(x, out);
    apply_scale_kernel<<<BB * CC, 1024>>>(out, ca_w1, ca_w2);
}

// round 17
// speedup vs baseline: 1.2750x; 1.2750x over previous
#include <cuda_runtime.h>
#include <cuda_fp16.h>
#include <cstdint>

#define BB 4
#define CC 64
#define C8 8
#define NN 9216          // 96*96
#define TN 128           // queries per CTA
#define TM 64            // key/value chunk
#define NCHUNK (NN/TM)   // 144
#define VSTH 80          // Vs row stride (halfs) = 160B
#define BUFB 11264       // per-buffer bytes: K 1024 + V 10240
#define SMEM_BYTES (4 * BUFB)   // 45056

typedef unsigned long long u64;

// ---------------- scratch ----------------
__device__ __half   g_Qh[(size_t)BB * NN * C8];          // [b][n][k] f16, pre-halved
__device__ __half   g_Kh[(size_t)BB * NCHUNK * TM * C8]; // [b][ch][m][k] f16
__device__ __half   g_Vp[(size_t)BB * NCHUNK * CC * TM]; // [b][ch][c][m'] f16, m-perm
__device__ float    g_vsum[BB * CC];                     // 0.5 * sum_m V_f16 (atomic)
__device__ float    g_sum[BB * CC];                      // sum over n of out (atomic)
__device__ uint32_t g_mxk[BB * CC];                      // max over n (key-coded)

__device__ __forceinline__ float th(float x) {      // MUFU.TANH f32
    asm("tanh.approx.f32 %0, %0;" : "+f"(x));
    return x;
}
__device__ __forceinline__ uint32_t pk(float lo, float hi) {  // f16x2 {lo,hi}
    uint32_t r;
    asm("cvt.rn.f16x2.f32 %0, %1, %2;" : "=r"(r) : "f"(hi), "f"(lo));
    return r;
}
__device__ __forceinline__ uint32_t smem_u32(const void* p) {
    uint32_t a;
    asm("{ .reg .u64 t; cvta.to.shared.u64 t, %1; cvt.u32.u64 %0, t; }" : "=r"(a) : "l"(p));
    return a;
}
__device__ __forceinline__ uint32_t fkey(float f) {
    uint32_t u = __float_as_uint(f);
    return (u >> 31) ? ~u : (u | 0x80000000u);
}
__device__ __forceinline__ float fdec(uint32_t k) {
    return (k >> 31) ? __uint_as_float(k & 0x7FFFFFFFu) : __uint_as_float(~k);
}
__device__ __forceinline__ u64 f2_fma(u64 a, u64 b, u64 c) {
    u64 d;
    asm("fma.rn.f32x2 %0, %1, %2, %3;" : "=l"(d) : "l"(a), "l"(b), "l"(c));
    return d;
}
__device__ __forceinline__ u64 f2_pack(float lo, float hi) {
    u64 d; asm("mov.b64 %0, {%1, %2};" : "=l"(d) : "f"(lo), "f"(hi)); return d;
}
__device__ __forceinline__ void f2_unpack(u64 v, float &lo, float &hi) {
    asm("mov.b64 {%0, %1}, %2;" : "=f"(lo), "=f"(hi) : "l"(v));
}

// m16n8k8 f16 -> f32
__device__ __forceinline__ void mma8h(float d[4], uint32_t a0, uint32_t a1, uint32_t b0) {
    asm volatile(
        "mma.sync.aligned.m16n8k8.row.col.f32.f16.f16.f32 "
        "{%0,%1,%2,%3}, {%4,%5}, {%6}, {%0,%1,%2,%3};"
        : "+f"(d[0]), "+f"(d[1]), "+f"(d[2]), "+f"(d[3])
        : "r"(a0), "r"(a1), "r"(b0));
}
// m16n8k16 f16 -> f32
__device__ __forceinline__ void mma16(float d[4], const uint32_t a[4], uint32_t b0, uint32_t b1) {
    asm volatile(
        "mma.sync.aligned.m16n8k16.row.col.f32.f16.f16.f32 "
        "{%0,%1,%2,%3}, {%4,%5,%6,%7}, {%8,%9}, {%0,%1,%2,%3};"
        : "+f"(d[0]), "+f"(d[1]), "+f"(d[2]), "+f"(d[3])
        : "r"(a[0]), "r"(a[1]), "r"(a[2]), "r"(a[3]), "r"(b0), "r"(b1));
}

#define CP16(dst, src) \
    asm volatile("cp.async.cg.shared.global [%0], [%1], 16;" :: "r"(dst), "l"(src))
#define CP_COMMIT() asm volatile("cp.async.commit_group;" ::: "memory")
#define CP_WAIT0()  asm volatile("cp.async.wait_group 0;" ::: "memory")
#define CP_WAIT1()  asm volatile("cp.async.wait_group 1;" ::: "memory")

// ---------------- kernel 0: zero accumulators (graph-replay safe) ------------
__global__ void init_kernel()
{
    int t = threadIdx.x;
    g_vsum[t] = 0.0f;
    g_sum[t]  = 0.0f;
    g_mxk[t]  = 0u;
}

// ---------------- kernel 1: fused 1x1-conv Q/K/V + vsum reduction ------------
__global__ __launch_bounds__(256) void qkv_kernel(
    const float* __restrict__ x,
    const float* __restrict__ wq, const float* __restrict__ bq,
    const float* __restrict__ wk, const float* __restrict__ bk,
    const float* __restrict__ wv, const float* __restrict__ bv)
{
    __shared__ float sw[80 * 64];
    __shared__ float sb[80];
    __shared__ float svs[8 * 64];     // per-warp vsum partials
    int tid = threadIdx.x;
    int wid = tid >> 5, lid = tid & 31;
    for (int i = tid; i < 512;  i += 256) sw[i] = wq[i];
    for (int i = tid; i < 512;  i += 256) sw[512 + i] = wk[i];
    for (int i = tid; i < 4096; i += 256) sw[1024 + i] = wv[i];
    if (tid < 80) sb[tid] = (tid < 8) ? bq[tid] : (tid < 16 ? bk[tid - 8] : bv[tid - 16]);
    __syncthreads();

    int n = blockIdx.x * 256 + tid;
    int b = blockIdx.y;
    const float* xb = x + (size_t)b * CC * NN + n;
    u64 xp[32];
    #pragma unroll
    for (int c = 0; c < 32; c++)
        xp[c] = f2_pack(xb[(size_t)(2 * c) * NN], xb[(size_t)(2 * c + 1) * NN]);

    const int ch = n >> 6;
    const int m  = n & 63;
    const int P = (m & 15) >> 1;
    const int mphys = (m & ~15) | ((((P & 3) * 2 + (P >> 2)) << 1) | (m & 1));

    float qv[8], kv[8];
    #pragma unroll 1
    for (int o = 0; o < C8; o++) {
        const u64* wqr = (const u64*)(sw + o * 64);
        const u64* wkr = (const u64*)(sw + 512 + o * 64);
        u64 aq2 = 0ULL, ak2 = 0ULL;
        #pragma unroll
        for (int c = 0; c < 32; c++) {
            aq2 = f2_fma(wqr[c], xp[c], aq2);
            ak2 = f2_fma(wkr[c], xp[c], ak2);
        }
        float ql, qh, kl, kh;
        f2_unpack(aq2, ql, qh); f2_unpack(ak2, kl, kh);
        qv[o] = 0.5f * (sb[o] + ql + qh);       // fold tanh's /2 into Q
        kv[o] = sb[8 + o] + kl + kh;
    }
    {
        uint32_t qw[4], kw[4];
        #pragma unroll
        for (int i = 0; i < 4; i++) {
            qw[i] = pk(qv[2 * i], qv[2 * i + 1]);
            kw[i] = pk(kv[2 * i], kv[2 * i + 1]);
        }
        *(uint4*)(g_Qh + ((size_t)b * NN + n) * C8) = make_uint4(qw[0], qw[1], qw[2], qw[3]);
        *(uint4*)(g_Kh + ((size_t)(b * NCHUNK + ch) * TM + m) * C8) =
            make_uint4(kw[0], kw[1], kw[2], kw[3]);
    }
    __half* vtile = g_Vp + ((size_t)(b * NCHUNK + ch) * CC) * TM;
    #pragma unroll 1
    for (int o = 0; o < CC; o++) {
        const u64* wvr = (const u64*)(sw + 1024 + o * 64);
        u64 av2 = 0ULL;
        #pragma unroll
        for (int c = 0; c < 32; c++) av2 = f2_fma(wvr[c], xp[c], av2);
        float vl, vh;
        f2_unpack(av2, vl, vh);
        __half hv = __float2half_rn(sb[16 + o] + vl + vh);
        vtile[o * TM + mphys] = hv;
        // vsum reduction: sum the f16-ROUNDED value (bit-consistent with GEMM2)
        float pv = __half2float(hv);
        #pragma unroll
        for (int off = 16; off > 0; off >>= 1)
            pv += __shfl_down_sync(0xFFFFFFFFu, pv, off);
        if (lid == 0) svs[wid * 64 + o] = pv;
    }
    __syncthreads();
    if (tid < 64) {
        float s = 0.f;
        #pragma unroll
        for (int w = 0; w < 8; w++) s += svs[w * 64 + tid];
        atomicAdd(&g_vsum[b * CC + tid], 0.5f * s);
    }
}

// ---------------- kernel 2: tanh-attention, af pipelined by one chunk --------
// (R15 verbatim — 8 warps; warp w owns n rows [w*16, w*16+16), all 64 m.)
__global__ __launch_bounds__(256, 2) void attn_mma_kernel(
    const float* __restrict__ x, float* __restrict__ out)
{
    extern __shared__ char sh[];
    const uint32_t sb = smem_u32(sh);

    const int tid = threadIdx.x, wid = tid >> 5, lid = tid & 31;
    const int g = lid >> 2, t = lid & 3;
    const int b = blockIdx.y, n0 = blockIdx.x * TN;

    uint32_t qa0, qa1;
    {
        const uint32_t* q0 = (const uint32_t*)(g_Qh + ((size_t)b * NN + n0 + wid * 16 + g) * C8);
        qa0 = q0[t];
        qa1 = q0[t + 32];
    }

    float acc[8][4];
    #pragma unroll
    for (int j = 0; j < 8; j++)
        #pragma unroll
        for (int k = 0; k < 4; k++) acc[j][k] = 0.0f;

    const __half* kbase = g_Kh + (size_t)b * NCHUNK * TM * C8;
    const __half* vbase = g_Vp + (size_t)b * NCHUNK * CC * TM;

    auto stage = [&](int ch, int buf) {
        uint32_t base = sb + buf * BUFB;
        if (tid < 64)
            CP16(base + tid * 16, (const char*)(kbase + (size_t)ch * TM * C8) + tid * 16);
        #pragma unroll
        for (int r = 0; r < 2; r++) {
            int pc = tid + r * 256;
            int c = pc >> 3, seg = pc & 7;
            CP16(base + 1024 + (uint32_t)(c * 160 + seg * 16),
                 (const char*)(vbase + (size_t)ch * CC * TM + c * TM) + seg * 16);
        }
    };

    auto gemm1_slice = [&](int buf, int ks, uint32_t af[4]) {
        const uint32_t* Ks = (const uint32_t*)(sh + buf * BUFB);
        float e0[4], e1[4];
        e0[0] = e0[1] = e0[2] = e0[3] = 0.0f;
        e1[0] = e1[1] = e1[2] = e1[3] = 0.0f;
        uint32_t kb0 = Ks[(ks * 16 + g) * 4 + t];
        uint32_t kb1 = Ks[(ks * 16 + 8 + g) * 4 + t];
        mma8h(e0, qa0, qa1, kb0);
        mma8h(e1, qa0, qa1, kb1);
        af[0] = pk(th(e0[0]), th(e0[1]));
        af[1] = pk(th(e0[2]), th(e0[3]));
        af[2] = pk(th(e1[0]), th(e1[1]));
        af[3] = pk(th(e1[2]), th(e1[3]));
    };

    auto gemm2_slice = [&](int buf, int ks, const uint32_t af[4]) {
        const __half* Vs = (const __half*)(sh + buf * BUFB + 1024);
        #pragma unroll
        for (int j = 0; j < 8; j++) {
            uint2 bv = *(const uint2*)(Vs + (8 * j + g) * VSTH + ks * 16 + 4 * t);
            mma16(acc[j], af, bv.x, bv.y);
        }
    };

    uint32_t af[4][4];

    stage(0, 0); CP_COMMIT();
    stage(1, 1); CP_COMMIT();
    CP_WAIT1();
    __syncthreads();
    #pragma unroll
    for (int ks = 0; ks < 4; ks++) gemm1_slice(0, ks, af[ks]);

    #pragma unroll 1
    for (int ch = 0; ch < NCHUNK; ch++) {
        CP_WAIT0();
        __syncthreads();
        if (ch + 2 < NCHUNK) { stage(ch + 2, (ch + 2) & 3); CP_COMMIT(); }
        const int bufC = ch & 3, bufN = (ch + 1) & 3;
        if (ch + 1 < NCHUNK) {
            #pragma unroll
            for (int ks = 0; ks < 4; ks++) {
                gemm2_slice(bufC, ks, af[ks]);
                gemm1_slice(bufN, ks, af[ks]);
            }
        } else {
            #pragma unroll
            for (int ks = 0; ks < 4; ks++)
                gemm2_slice(bufC, ks, af[ks]);
        }
    }

    // ---- epilogue: out = vsum + 0.5*acc + x; fused mean/max reduction ----
    const int n = n0 + wid * 16 + g;
    #pragma unroll
    for (int j = 0; j < 8; j++) {
        int c = 8 * j + 2 * t;
        float vs0 = g_vsum[b * CC + c];
        float vs1 = g_vsum[b * CC + c + 1];
        size_t i00 = ((size_t)b * CC + c) * NN + n;
        size_t i01 = i00 + NN;
        float f0  = fmaf(0.5f, acc[j][0], vs0) + x[i00];
        float f1  = fmaf(0.5f, acc[j][1], vs1) + x[i01];
        float f2v = fmaf(0.5f, acc[j][2], vs0) + x[i00 + 8];
        float f3  = fmaf(0.5f, acc[j][3], vs1) + x[i01 + 8];
        out[i00]     = f0;
        out[i01]     = f1;
        out[i00 + 8] = f2v;
        out[i01 + 8] = f3;

        float sc  = f0 + f2v,       sc1 = f1 + f3;
        float mc  = fmaxf(f0, f2v), mc1 = fmaxf(f1, f3);
        #pragma unroll
        for (int off = 16; off >= 4; off >>= 1) {
            sc  += __shfl_down_sync(0xFFFFFFFFu, sc,  off);
            sc1 += __shfl_down_sync(0xFFFFFFFFu, sc1, off);
            mc   = fmaxf(mc,  __shfl_down_sync(0xFFFFFFFFu, mc,  off));
            mc1  = fmaxf(mc1, __shfl_down_sync(0xFFFFFFFFu, mc1, off));
        }
        if (lid < 4) {
            atomicAdd(&g_sum[b * CC + c],     sc);
            atomicAdd(&g_sum[b * CC + c + 1], sc1);
            atomicMax(&g_mxk[b * CC + c],     fkey(mc));
            atomicMax(&g_mxk[b * CC + c + 1], fkey(mc1));
        }
    }
}

// ---------------- kernel 3: CBAM MLP + apply (512 thr, 2 CTAs per row) --------
__global__ __launch_bounds__(512) void apply_scale_kernel(
    float* __restrict__ out,
    const float* __restrict__ w1, const float* __restrict__ w2)
{
    const int bc = blockIdx.x;
    const int b = bc >> 6, c = bc & 63;
    const int tid = threadIdx.x, lane = tid & 31;

    // every warp computes the scale independently (no __syncthreads)
    float av0 = g_sum[b * CC + lane]      * (1.0f / NN);
    float av1 = g_sum[b * CC + lane + 32] * (1.0f / NN);
    float mx0 = fdec(g_mxk[b * CC + lane]);
    float mx1 = fdec(g_mxk[b * CC + lane + 32]);

    float y = 0.f;
    #pragma unroll
    for (int r = 0; r < 4; r++) {
        float w0  = w1[r * 64 + lane];
        float w2v = w1[r * 64 + lane + 32];
        float ha = w0 * av0 + w2v * av1;
        float hm = w0 * mx0 + w2v * mx1;
        #pragma unroll
        for (int off = 16; off > 0; off >>= 1) {
            ha += __shfl_xor_sync(0xFFFFFFFFu, ha, off);
            hm += __shfl_xor_sync(0xFFFFFFFFu, hm, off);
        }
        y += w2[c * 4 + r] * (fmaxf(ha, 0.f) + fmaxf(hm, 0.f));
    }
    const float s = 1.0f / (1.0f + expf(-y));

    const int half = blockIdx.y;
    float4* row = (float4*)(out + (size_t)bc * NN) + half * (NN / 8);
    for (int i = tid; i < NN / 8; i += 512) {
        float4 v = row[i];
        v.x *= s; v.y *= s; v.z *= s; v.w *= s;
        row[i] = v;
    }
}

// ---------------- launch ----------------
extern "C" void kernel_launch(void* const* d_in, const int* in_sizes, int n_in,
                              void* d_out, int out_size)
{
    const float* x     = (const float*)d_in[0];
    const float* wq    = (const float*)d_in[1];
    const float* bq    = (const float*)d_in[2];
    const float* wk    = (const float*)d_in[3];
    const float* bk    = (const float*)d_in[4];
    const float* wv    = (const float*)d_in[5];
    const float* bv    = (const float*)d_in[6];
    const float* ca_w1 = (const float*)d_in[7];
    const float* ca_w2 = (const float*)d_in[8];
    float* out = (float*)d_out;

    cudaFuncSetAttribute(attn_mma_kernel, cudaFuncAttributeMaxDynamicSharedMemorySize, SMEM_BYTES);

    init_kernel<<<1, 256>>>();
    qkv_kernel<<<dim3(NN / 256, BB), 256>>>(x, wq, bq, wk, bk, wv, bv);
    attn_mma_kernel<<<dim3(NN / TN, BB), 256, SMEM_BYTES>>>(x, out);
    apply_scale_kernel<<<dim3(BB * CC, 2), 512>>>(out, ca_w1, ca_w2);
}